// round 9
// baseline (speedup 1.0000x reference)
#include <cuda_runtime.h>
#include <math.h>
#include <stdint.h>

#define TT 2048
#define DIMD 2048
#define NH 16
#define NKVH 4
#define HD 128
#define NQ (NH*HD)     // 2048
#define NKV (NKVH*HD)  // 512
#define REP (NH/NKVH)  // 4
#define QKVW 3072      // packed qkv width

// Scratch (device globals; allocation in kernel_launch is forbidden)
__device__ float g_qkv[TT*QKVW];     // [T][3072]: Q | K | V
__device__ float g_att[TT*NQ];
__device__ float g_xr  [TT*DIMD];
__device__ float g_wqkv[QKVW*DIMD];  // rows: wq(2048) | wk(512) | wv(512)
__device__ float g_wor [DIMD*NQ];
__device__ unsigned g_ctr;           // FA work-steal counter

// ---------------------------------------------------------------------------
// helpers
// ---------------------------------------------------------------------------
__device__ __forceinline__ unsigned f2tf(float f) {
    unsigned u; asm("cvt.rna.tf32.f32 %0, %1;" : "=r"(u) : "f"(f)); return u;
}

#define R_X   (TT*DIMD/4)
#define R_WQ  (NQ*DIMD/4)
#define R_WKV (NKV*DIMD/4)
#define R_TOT (R_X + R_WQ + 2*R_WKV + NQ*DIMD/4)

__global__ void round_all_kernel(const float* __restrict__ x,
                                 const float* __restrict__ wq,
                                 const float* __restrict__ wk,
                                 const float* __restrict__ wv,
                                 const float* __restrict__ wo,
                                 float* __restrict__ xr,
                                 float* __restrict__ wqkv,
                                 float* __restrict__ wor)
{
    int i = blockIdx.x * blockDim.x + threadIdx.x;
    if (i >= R_TOT) return;
    const float* in; float* out; int j = i;
    if (j < R_X)                   { in = x;  out = xr; }
    else if ((j -= R_X)   < R_WQ)  { in = wq; out = wqkv; }
    else if ((j -= R_WQ)  < R_WKV) { in = wk; out = wqkv + (size_t)NQ*DIMD; }
    else if ((j -= R_WKV) < R_WKV) { in = wv; out = wqkv + (size_t)(NQ+NKV)*DIMD; }
    else { j -= R_WKV;               in = wo; out = wor; }
    float4 v = ((const float4*)in)[j];
    uint4 o;
    o.x = f2tf(v.x); o.y = f2tf(v.y); o.z = f2tf(v.z); o.w = f2tf(v.w);
    ((uint4*)out)[j] = o;
}

__device__ __forceinline__ void cp_async16(unsigned saddr, const void* g) {
    asm volatile("cp.async.cg.shared.global [%0], [%1], 16;\n"
                 :: "r"(saddr), "l"(g));
}
__device__ __forceinline__ void cp_commit() {
    asm volatile("cp.async.commit_group;\n");
}
__device__ __forceinline__ void cp_wait0() {
    asm volatile("cp.async.wait_group 0;\n");
}
__device__ __forceinline__ void cp_wait1() {
    asm volatile("cp.async.wait_group 1;\n");
}

__device__ __forceinline__ void mma_tf32(float c[4], const uint4& a,
                                         unsigned b0, unsigned b1) {
    asm volatile(
        "mma.sync.aligned.m16n8k8.row.col.f32.tf32.tf32.f32 "
        "{%0,%1,%2,%3}, {%4,%5,%6,%7}, {%8,%9}, {%0,%1,%2,%3};\n"
        : "+f"(c[0]), "+f"(c[1]), "+f"(c[2]), "+f"(c[3])
        : "r"(a.x), "r"(a.y), "r"(a.z), "r"(a.w), "r"(b0), "r"(b1));
}

__device__ __forceinline__ void ldsm_x4(uint4& d, unsigned addr) {
    asm volatile(
        "ldmatrix.sync.aligned.m8n8.x4.shared.b16 {%0,%1,%2,%3}, [%4];\n"
        : "=r"(d.x), "=r"(d.y), "=r"(d.z), "=r"(d.w) : "r"(addr));
}

// ---------------------------------------------------------------------------
// Tensor-core tf32 GEMM: C[2048,N] = A[2048,2048] * B[N,2048]^T.
// CTA tile 128x128, 256 threads (8 warps 4m x 2n), warp tile 32x64.
// BK=32, 3-stage cp.async ring, ONE barrier per k-iter. ~110 regs -> occ 2:
// the co-resident CTA fills pipeline gaps. smem 110592 B/CTA (2 fit in 228KB).
// Columns >= rt_col rounded to tf32 on output.
// ---------------------------------------------------------------------------
#define BKK 32
#define SAST 36
#define GK 2048
#define GASZ (128*SAST)
#define GSTG (2*GASZ)            // A + B per stage (9216 floats)
#define GEMM_SMEM (3*GSTG*4)     // 110592 bytes

__device__ __forceinline__ void gemm_tc(
    const float* __restrict__ A, const float* __restrict__ B,
    float* __restrict__ C, int N, int bm, int bn, int rt_col)
{
    extern __shared__ float smf[];
    int tid = threadIdx.x;
    int lane = tid & 31, wid = tid >> 5;
    int wm = (wid & 3) * 32;
    int wn = (wid >> 2) * 64;
    int g = lane >> 2, t = lane & 3;

    int lrow = lane & 7;
    int am   = lane >> 3;
    int a_row  = wm + ((am & 1) << 3) + lrow;
    int a_col4 = (am >> 1) << 2;
    int b_row  = wn + ((am >> 1) << 3) + lrow;
    int b_col4 = (am & 1) << 2;

    unsigned smem_base = (unsigned)__cvta_generic_to_shared(smf);

    float c[2][8][4];
#pragma unroll
    for (int mi = 0; mi < 2; mi++)
#pragma unroll
        for (int nj = 0; nj < 8; nj++)
#pragma unroll
            for (int r = 0; r < 4; r++) c[mi][nj][r] = 0.f;

    auto load_stage = [&](int s, int kt) {
        int k0 = kt * BKK;
        unsigned sa = smem_base + (unsigned)(s * GSTG) * 4u;
        unsigned sb = sa + (unsigned)GASZ * 4u;
#pragma unroll
        for (int i = 0; i < 4; i++) {
            int idx = tid + 256 * i;     // 0..1023
            int row = idx >> 3;          // 0..127
            int kc  = (idx & 7) * 4;
            cp_async16(sa + (unsigned)(row * SAST + kc) * 4u,
                       &A[(size_t)(bm + row) * GK + k0 + kc]);
            cp_async16(sb + (unsigned)(row * SAST + kc) * 4u,
                       &B[(size_t)(bn + row) * GK + k0 + kc]);
        }
        cp_commit();
    };

    load_stage(0, 0);
    load_stage(1, 1);
    const int KT = GK / BKK;

    int st = 0;   // = kt % 3
    for (int kt = 0; kt < KT; kt++) {
        if (kt + 1 < KT) cp_wait1(); else cp_wait0();
        __syncthreads();
        // stage (kt+2)%3 was last read in iter kt-1; all warps passed the
        // barrier above, so overwriting it now is safe.
        if (kt + 2 < KT) {
            int s2 = st + 2; if (s2 >= 3) s2 -= 3;
            load_stage(s2, kt + 2);
        }

        unsigned sA = smem_base + (unsigned)(st * GSTG) * 4u;
        unsigned sB = sA + (unsigned)GASZ * 4u;

#pragma unroll
        for (int ks = 0; ks < 4; ks++) {
            int k0 = ks * 8;
            uint4 a[2], bp[4];
#pragma unroll
            for (int mi = 0; mi < 2; mi++)
                ldsm_x4(a[mi], sA + (unsigned)((a_row + mi*16) * SAST
                                               + k0 + a_col4) * 4u);
#pragma unroll
            for (int p = 0; p < 4; p++)
                ldsm_x4(bp[p], sB + (unsigned)((b_row + p*16) * SAST
                                               + k0 + b_col4) * 4u);
#pragma unroll
            for (int mi = 0; mi < 2; mi++)
#pragma unroll
                for (int p = 0; p < 4; p++) {
                    mma_tf32(c[mi][2*p  ], a[mi], bp[p].x, bp[p].y);
                    mma_tf32(c[mi][2*p+1], a[mi], bp[p].z, bp[p].w);
                }
        }
        if (++st == 3) st = 0;
    }

#pragma unroll
    for (int mi = 0; mi < 2; mi++) {
#pragma unroll
        for (int nj = 0; nj < 8; nj++) {
            int row0 = bm + wm + mi * 16 + g;
            int col  = bn + wn + nj * 8 + 2 * t;
            float v0 = c[mi][nj][0], v1 = c[mi][nj][1];
            float v2 = c[mi][nj][2], v3 = c[mi][nj][3];
            if (col >= rt_col) {
                v0 = __uint_as_float(f2tf(v0)); v1 = __uint_as_float(f2tf(v1));
                v2 = __uint_as_float(f2tf(v2)); v3 = __uint_as_float(f2tf(v3));
            }
            *(float2*)&C[(size_t)row0 * N + col]       = make_float2(v0, v1);
            *(float2*)&C[(size_t)(row0 + 8) * N + col] = make_float2(v2, v3);
        }
    }
}

// Packed QKV projection: grid (24, 16). V columns (>=2560) rounded to tf32.
__global__ __launch_bounds__(256, 2) void qkv_gemm_kernel(
    const float* __restrict__ A, const float* __restrict__ B,
    float* __restrict__ C)
{
    gemm_tc(A, B, C, QKVW, blockIdx.y * 128, blockIdx.x * 128,
            NQ + NKV /* 2560 */);
}

// Output projection: grid (16, 16).
__global__ __launch_bounds__(256, 2) void oproj_gemm_kernel(
    const float* __restrict__ A, const float* __restrict__ B,
    float* __restrict__ C)
{
    gemm_tc(A, B, C, DIMD, blockIdx.y * 128, blockIdx.x * 128, 0x40000000);
}

// ---------------------------------------------------------------------------
// Fused RoPE over Q (16 heads, scaled) and K (4 heads) in packed g_qkv.
// ---------------------------------------------------------------------------
__global__ void rope_fused_kernel(float* __restrict__ qkv,
                                  const float* __restrict__ cs,
                                  const float* __restrict__ sn, float qscale)
{
    int idx = blockIdx.x * blockDim.x + threadIdx.x;  // TT*20*64 threads
    int i  = idx & 63;
    int hh = (idx >> 6) % 20;
    int t  = idx / (64 * 20);
    if (t >= TT) return;
    float c = cs[t * HD + i];
    float s = sn[t * HD + i];
    float* p;
    float scale;
    if (hh < NH) { p = qkv + (size_t)t * QKVW + hh * HD;            scale = qscale; }
    else         { p = qkv + (size_t)t * QKVW + NQ + (hh - NH) * HD; scale = 1.0f; }
    float u1 = p[i], u2 = p[i + 64];
    p[i]      = __uint_as_float(f2tf((u1 * c - u2 * s) * scale));
    p[i + 64] = __uint_as_float(f2tf((u2 * c + u1 * s) * scale));
}

// ---------------------------------------------------------------------------
// Tensor-core flash attention (tf32, legacy mma). BQ=128, BKV=64, 256 thr.
// PERSISTENT + WORK-STEAL: grid = #SMs; items handed out heavy-first via
// atomic counter (g_ctr zeroed by cudaMemsetAsync before launch).
// Item r: qb = 15 - (r>>4), h = r & 15.
// ---------------------------------------------------------------------------
#define FAQ 128
#define FA_QST 132
#define FA_VST 136
#define FA_QSZ (FAQ*FA_QST)
#define FA_KSZ (64*FA_QST)
#define FA_KVSZ (FA_KSZ + 64*FA_VST)
#define FA_SMEM ((FA_QSZ + 2*FA_KVSZ)*4)
#define FA_ITEMS (NH * (TT/FAQ))   // 256

__global__ __launch_bounds__(256, 1) void fa_tc_kernel(float* __restrict__ att)
{
    extern __shared__ float smf[];
    __shared__ unsigned s_item;
    int tid = threadIdx.x;
    int lane = tid & 31, wid = tid >> 5;
    int g = lane >> 2, t = lane & 3;
    int w16 = wid * 16;

    int lrow = lane & 7;
    int am   = lane >> 3;
    int a_row  = w16 + ((am & 1) << 3) + lrow;
    int a_col4 = (am >> 1) << 2;
    int b_row  = ((am >> 1) << 3) + lrow;
    int b_col4 = (am & 1) << 2;

    unsigned smem_base = (unsigned)__cvta_generic_to_shared(smf);
    float* Qs = smf;

    while (true) {
        if (tid == 0) s_item = atomicAdd(&g_ctr, 1u);
        __syncthreads();
        unsigned r = s_item;
        if (r >= FA_ITEMS) break;
        int qb = (TT/FAQ) - 1 - (int)(r >> 4);
        int h  = (int)(r & 15u);
        int g0 = h / REP;

#pragma unroll
        for (int i = 0; i < 16; i++) {
            int idx = tid + 256 * i;
            int rr = idx >> 5;
            int c4 = (idx & 31) * 4;
            *(float4*)&Qs[rr*FA_QST + c4] =
                *(const float4*)&g_qkv[(size_t)(qb*FAQ + rr) * QKVW + h*HD + c4];
        }

        auto load_kv = [&](int kb, int s) {
            const float* Kg = &g_qkv[(size_t)(kb*64) * QKVW + NQ + g0*HD];
            const float* Vg = Kg + NKV;
            unsigned kbase = smem_base + (unsigned)(FA_QSZ + s*FA_KVSZ) * 4u;
            unsigned vbase = kbase + (unsigned)FA_KSZ * 4u;
#pragma unroll
            for (int i = 0; i < 8; i++) {
                int idx = tid + 256 * i;
                int rr = idx >> 5;
                int c4 = (idx & 31) * 4;
                cp_async16(kbase + (unsigned)(rr*FA_QST + c4) * 4u,
                           Kg + (size_t)rr*QKVW + c4);
                cp_async16(vbase + (unsigned)(rr*FA_VST + c4) * 4u,
                           Vg + (size_t)rr*QKVW + c4);
            }
            cp_commit();
        };

        float o[16][4];
#pragma unroll
        for (int nj = 0; nj < 16; nj++)
#pragma unroll
            for (int rr = 0; rr < 4; rr++) o[nj][rr] = 0.f;
        float m0 = -1e30f, m1 = -1e30f, l0 = 0.f, l1 = 0.f;

        const int kb_max = 2*qb + 1;
        load_kv(0, 0);

        for (int kb = 0; kb <= kb_max; kb++) {
            if (kb < kb_max) { load_kv(kb + 1, (kb + 1) & 1); cp_wait1(); }
            else             { cp_wait0(); }
            __syncthreads();

            unsigned sK = smem_base + (unsigned)(FA_QSZ + (kb & 1)*FA_KVSZ) * 4u;
            const float* Vs = smf + FA_QSZ + (kb & 1)*FA_KVSZ + FA_KSZ;

            float s[8][4];
#pragma unroll
            for (int nj = 0; nj < 8; nj++)
#pragma unroll
                for (int rr = 0; rr < 4; rr++) s[nj][rr] = 0.f;

            // ---- S = Q K^T with fragment double buffering ----
            uint4 a2[2], bp2[2][4];
            ldsm_x4(a2[0], smem_base + (unsigned)(a_row*FA_QST + a_col4)*4u);
#pragma unroll
            for (int p = 0; p < 4; p++)
                ldsm_x4(bp2[0][p], sK + (unsigned)((b_row + p*16)*FA_QST
                                                   + b_col4)*4u);
#pragma unroll
            for (int ks = 0; ks < 16; ks++) {
                int cur = ks & 1;
                if (ks < 15) {
                    int kn = (ks + 1) * 8;
                    ldsm_x4(a2[cur ^ 1],
                            smem_base + (unsigned)(a_row*FA_QST + kn + a_col4)*4u);
#pragma unroll
                    for (int p = 0; p < 4; p++)
                        ldsm_x4(bp2[cur ^ 1][p],
                                sK + (unsigned)((b_row + p*16)*FA_QST
                                                + kn + b_col4)*4u);
                }
#pragma unroll
                for (int p = 0; p < 4; p++) {
                    mma_tf32(s[2*p  ], a2[cur], bp2[cur][p].x, bp2[cur][p].y);
                    mma_tf32(s[2*p+1], a2[cur], bp2[cur][p].z, bp2[cur][p].w);
                }
            }

            if (kb >= 2*qb) {
                int r0 = qb*FAQ + w16 + g, r1 = r0 + 8;
                int cb0 = kb*64 + 2*t;
#pragma unroll
                for (int nj = 0; nj < 8; nj++) {
                    int c0 = cb0 + nj*8, c1 = c0 + 1;
                    if (c0 > r0) s[nj][0] = -1e30f;
                    if (c1 > r0) s[nj][1] = -1e30f;
                    if (c0 > r1) s[nj][2] = -1e30f;
                    if (c1 > r1) s[nj][3] = -1e30f;
                }
            }

            float mx0 = -1e30f, mx1 = -1e30f;
#pragma unroll
            for (int nj = 0; nj < 8; nj++) {
                mx0 = fmaxf(mx0, fmaxf(s[nj][0], s[nj][1]));
                mx1 = fmaxf(mx1, fmaxf(s[nj][2], s[nj][3]));
            }
            mx0 = fmaxf(mx0, __shfl_xor_sync(0xffffffffu, mx0, 1));
            mx0 = fmaxf(mx0, __shfl_xor_sync(0xffffffffu, mx0, 2));
            mx1 = fmaxf(mx1, __shfl_xor_sync(0xffffffffu, mx1, 1));
            mx1 = fmaxf(mx1, __shfl_xor_sync(0xffffffffu, mx1, 2));
            float mn0 = fmaxf(m0, mx0), mn1 = fmaxf(m1, mx1);
            float al0 = __expf(m0 - mn0), al1 = __expf(m1 - mn1);
            m0 = mn0; m1 = mn1;

            float rs0 = 0.f, rs1 = 0.f;
#pragma unroll
            for (int nj = 0; nj < 8; nj++) {
                s[nj][0] = __expf(s[nj][0] - mn0);
                s[nj][1] = __expf(s[nj][1] - mn0);
                s[nj][2] = __expf(s[nj][2] - mn1);
                s[nj][3] = __expf(s[nj][3] - mn1);
                rs0 += s[nj][0] + s[nj][1];
                rs1 += s[nj][2] + s[nj][3];
            }
            rs0 += __shfl_xor_sync(0xffffffffu, rs0, 1);
            rs0 += __shfl_xor_sync(0xffffffffu, rs0, 2);
            rs1 += __shfl_xor_sync(0xffffffffu, rs1, 1);
            rs1 += __shfl_xor_sync(0xffffffffu, rs1, 2);
            l0 = l0 * al0 + rs0;
            l1 = l1 * al1 + rs1;

#pragma unroll
            for (int nj = 0; nj < 16; nj++) {
                o[nj][0] *= al0; o[nj][1] *= al0;
                o[nj][2] *= al1; o[nj][3] *= al1;
            }

            // ---- O += P @ V with software-pipelined V loads ----
            int src0 = (lane & ~3) + (t >> 1);
            int src1 = src0 + 2;
#pragma unroll
            for (int kt = 0; kt < 8; kt++) {
                unsigned vb0 = __float_as_uint(Vs[(kt*8 + t    )*FA_VST + g]);
                unsigned vb1 = __float_as_uint(Vs[(kt*8 + t + 4)*FA_VST + g]);
                float p00 = __shfl_sync(0xffffffffu, s[kt][0], src0);
                float p01 = __shfl_sync(0xffffffffu, s[kt][1], src0);
                float p20 = __shfl_sync(0xffffffffu, s[kt][2], src0);
                float p21 = __shfl_sync(0xffffffffu, s[kt][3], src0);
                float q00 = __shfl_sync(0xffffffffu, s[kt][0], src1);
                float q01 = __shfl_sync(0xffffffffu, s[kt][1], src1);
                float q20 = __shfl_sync(0xffffffffu, s[kt][2], src1);
                float q21 = __shfl_sync(0xffffffffu, s[kt][3], src1);
                uint4 a;
                a.x = f2tf((t & 1) ? p01 : p00);
                a.y = f2tf((t & 1) ? p21 : p20);
                a.z = f2tf((t & 1) ? q01 : q00);
                a.w = f2tf((t & 1) ? q21 : q20);
#pragma unroll
                for (int nj = 0; nj < 16; nj++) {
                    unsigned nb0, nb1;
                    if (nj < 15) {
                        nb0 = __float_as_uint(Vs[(kt*8 + t    )*FA_VST + (nj+1)*8 + g]);
                        nb1 = __float_as_uint(Vs[(kt*8 + t + 4)*FA_VST + (nj+1)*8 + g]);
                    }
                    mma_tf32(o[nj], a, vb0, vb1);
                    if (nj < 15) { vb0 = nb0; vb1 = nb1; }
                }
            }
            __syncthreads();
        }

        float il0 = 1.0f / l0, il1 = 1.0f / l1;
#pragma unroll
        for (int nj = 0; nj < 16; nj++) {
            int row0 = qb*FAQ + w16 + g;
            int col  = h*HD + nj*8 + 2*t;
            float2 v0 = make_float2(__uint_as_float(f2tf(o[nj][0]*il0)),
                                    __uint_as_float(f2tf(o[nj][1]*il0)));
            float2 v1 = make_float2(__uint_as_float(f2tf(o[nj][2]*il1)),
                                    __uint_as_float(f2tf(o[nj][3]*il1)));
            *(float2*)&att[(size_t)row0 * NQ + col]       = v0;
            *(float2*)&att[(size_t)(row0 + 8) * NQ + col] = v1;
        }
        __syncthreads();   // all reads of s_item done before next steal
    }
}

// ---------------------------------------------------------------------------
extern "C" void kernel_launch(void* const* d_in, const int* in_sizes, int n_in,
                              void* d_out, int out_size)
{
    const float* x  = (const float*)d_in[0];
    const float* wq = (const float*)d_in[1];
    const float* wk = (const float*)d_in[2];
    const float* wv = (const float*)d_in[3];
    const float* wo = (const float*)d_in[4];
    const float* cs = (const float*)d_in[5];
    const float* sn = (const float*)d_in[6];
    float* out = (float*)d_out;

    float *qkv, *att, *xr, *wqkv, *wor;
    void* ctr;
    cudaGetSymbolAddress((void**)&qkv,  g_qkv);
    cudaGetSymbolAddress((void**)&att,  g_att);
    cudaGetSymbolAddress((void**)&xr,   g_xr);
    cudaGetSymbolAddress((void**)&wqkv, g_wqkv);
    cudaGetSymbolAddress((void**)&wor,  g_wor);
    cudaGetSymbolAddress(&ctr,          g_ctr);

    static int nsm = 0;
    if (nsm == 0) {
        cudaDeviceGetAttribute(&nsm, cudaDevAttrMultiProcessorCount, 0);
        if (nsm <= 0) nsm = 148;
        cudaFuncSetAttribute(qkv_gemm_kernel,
            cudaFuncAttributeMaxDynamicSharedMemorySize, GEMM_SMEM);
        cudaFuncSetAttribute(oproj_gemm_kernel,
            cudaFuncAttributeMaxDynamicSharedMemorySize, GEMM_SMEM);
        cudaFuncSetAttribute(fa_tc_kernel,
            cudaFuncAttributeMaxDynamicSharedMemorySize, FA_SMEM);
    }

    // Pre-round all GEMM inputs to tf32 (weights packed into g_wqkv)
    round_all_kernel<<<(R_TOT + 255)/256, 256>>>(
        x, wq, wk, wv, wo, xr, wqkv, wor);

    // Packed QKV projection: 128x128 tiles at occupancy 2
    qkv_gemm_kernel<<<dim3(QKVW/128, TT/128), 256, GEMM_SMEM>>>(xr, wqkv, qkv);

    // Fused RoPE over Q and K (rounds to tf32; Q gets 1/sqrt(HD) folded in)
    const float scale = 0.08838834764831845f;  // 128^-0.5
    rope_fused_kernel<<<(TT*20*64)/256, 256>>>(qkv, cs, sn, scale);

    // Flash attention: persistent work-steal over all SMs
    cudaMemsetAsync(ctr, 0, sizeof(unsigned));
    fa_tc_kernel<<<dim3(nsm, 1), 256, FA_SMEM>>>(att);

    // Output projection: 128x128 tiles at occupancy 2
    oproj_gemm_kernel<<<dim3(DIMD/128, TT/128), 256, GEMM_SMEM>>>(att, wor, out);
}

// round 10
// speedup vs baseline: 1.6561x; 1.6561x over previous
#include <cuda_runtime.h>
#include <cuda_fp16.h>
#include <math.h>
#include <stdint.h>

#define TT 2048
#define DIMD 2048
#define NH 16
#define NKVH 4
#define HD 128
#define NQ (NH*HD)     // 2048
#define NKV (NKVH*HD)  // 512
#define REP (NH/NKVH)  // 4
#define QKVW 3072

// Scratch (device globals; allocation in kernel_launch is forbidden)
__device__ float  g_qkv [TT*QKVW];    // fp32 QKV GEMM output
__device__ __half g_qkvh[TT*QKVW];    // fp16 Q(roped)|K(roped)|V
__device__ __half g_atth[TT*NQ];      // fp16 attention output
__device__ __half g_xh  [TT*DIMD];
__device__ __half g_wqkvh[QKVW*DIMD]; // rows: wq | wk | wv
__device__ __half g_worh[DIMD*NQ];
__device__ unsigned g_ctr;

// ---------------------------------------------------------------------------
// helpers
// ---------------------------------------------------------------------------
#define R_X   (TT*DIMD/4)
#define R_WQ  (NQ*DIMD/4)
#define R_WKV (NKV*DIMD/4)
#define R_TOT (R_X + R_WQ + 2*R_WKV + NQ*DIMD/4)

__global__ void round_all_kernel(const float* __restrict__ x,
                                 const float* __restrict__ wq,
                                 const float* __restrict__ wk,
                                 const float* __restrict__ wv,
                                 const float* __restrict__ wo,
                                 __half* __restrict__ xh,
                                 __half* __restrict__ wqkvh,
                                 __half* __restrict__ worh)
{
    int i = blockIdx.x * blockDim.x + threadIdx.x;
    if (i >= R_TOT) return;
    const float* in; __half* out; int j = i;
    if (j < R_X)                   { in = x;  out = xh; }
    else if ((j -= R_X)   < R_WQ)  { in = wq; out = wqkvh; }
    else if ((j -= R_WQ)  < R_WKV) { in = wk; out = wqkvh + (size_t)NQ*DIMD; }
    else if ((j -= R_WKV) < R_WKV) { in = wv; out = wqkvh + (size_t)(NQ+NKV)*DIMD; }
    else { j -= R_WKV;               in = wo; out = worh; }
    float4 v = ((const float4*)in)[j];
    __half2 h0 = __floats2half2_rn(v.x, v.y);
    __half2 h1 = __floats2half2_rn(v.z, v.w);
    ((__half2*)out)[2*j]   = h0;
    ((__half2*)out)[2*j+1] = h1;
}

__device__ __forceinline__ void cp_async16(unsigned saddr, const void* g) {
    asm volatile("cp.async.cg.shared.global [%0], [%1], 16;\n"
                 :: "r"(saddr), "l"(g));
}
__device__ __forceinline__ void cp_commit() {
    asm volatile("cp.async.commit_group;\n");
}
__device__ __forceinline__ void cp_wait0() {
    asm volatile("cp.async.wait_group 0;\n");
}
__device__ __forceinline__ void cp_wait1() {
    asm volatile("cp.async.wait_group 1;\n");
}

// fp16 mma m16n8k16, fp32 accum
__device__ __forceinline__ void mma_f16(float c[4], const uint4& a,
                                        unsigned b0, unsigned b1) {
    asm volatile(
        "mma.sync.aligned.m16n8k16.row.col.f32.f16.f16.f32 "
        "{%0,%1,%2,%3}, {%4,%5,%6,%7}, {%8,%9}, {%0,%1,%2,%3};\n"
        : "+f"(c[0]), "+f"(c[1]), "+f"(c[2]), "+f"(c[3])
        : "r"(a.x), "r"(a.y), "r"(a.z), "r"(a.w), "r"(b0), "r"(b1));
}

__device__ __forceinline__ void ldsm_x4(uint4& d, unsigned addr) {
    asm volatile(
        "ldmatrix.sync.aligned.m8n8.x4.shared.b16 {%0,%1,%2,%3}, [%4];\n"
        : "=r"(d.x), "=r"(d.y), "=r"(d.z), "=r"(d.w) : "r"(addr));
}
__device__ __forceinline__ void ldsm_x4_t(uint4& d, unsigned addr) {
    asm volatile(
        "ldmatrix.sync.aligned.m8n8.x4.trans.shared.b16 {%0,%1,%2,%3}, [%4];\n"
        : "=r"(d.x), "=r"(d.y), "=r"(d.z), "=r"(d.w) : "r"(addr));
}

__device__ __forceinline__ unsigned pack_h2(float lo, float hi) {
    __half2 h = __floats2half2_rn(lo, hi);
    return *reinterpret_cast<unsigned*>(&h);
}

// ---------------------------------------------------------------------------
// fp16 GEMM: C[2048,N](fp32) = A[2048,2048](fp16) * B[N,2048](fp16)^T.
// CTA 128x128, 256 threads (8 warps 4m x 2n), warp tile 32x64.
// BK=32 halves, 3-stage cp.async ring, one barrier per k-iter, occ 2.
// ---------------------------------------------------------------------------
#define BKK 32
#define SASTH 40                 // smem row stride in halves (80 B)
#define GK 2048
#define GASZH (128*SASTH)        // 5120 halves per operand
#define GSTGH (2*GASZH)          // 10240 halves per stage
#define GEMM_SMEM (3*GSTGH*2)    // 61440 bytes

__device__ __forceinline__ void gemm_f16(
    const __half* __restrict__ A, const __half* __restrict__ B,
    float* __restrict__ C, int N, int bm, int bn)
{
    extern __shared__ float smf[];
    __half* smh = (__half*)smf;
    int tid = threadIdx.x;
    int lane = tid & 31, wid = tid >> 5;
    int wm = (wid & 3) * 32;
    int wn = (wid >> 2) * 64;
    int g = lane >> 2, t = lane & 3;

    int lrow = lane & 7;
    int am   = lane >> 3;
    int a_row  = wm + ((am & 1) << 3) + lrow;   // A: m&1 -> row half, m>>1 -> k half
    int a_colh = (am >> 1) << 3;
    int b_row  = wn + ((am >> 1) << 3) + lrow;  // B: m>>1 -> n half, m&1 -> k half
    int b_colh = (am & 1) << 3;

    unsigned smem_base = (unsigned)__cvta_generic_to_shared(smh);

    float c[2][8][4];
#pragma unroll
    for (int mi = 0; mi < 2; mi++)
#pragma unroll
        for (int nj = 0; nj < 8; nj++)
#pragma unroll
            for (int r = 0; r < 4; r++) c[mi][nj][r] = 0.f;

    auto load_stage = [&](int s, int kt) {
        int k0 = kt * BKK;
        unsigned sa = smem_base + (unsigned)(s * GSTGH) * 2u;
        unsigned sb = sa + (unsigned)GASZH * 2u;
#pragma unroll
        for (int i = 0; i < 2; i++) {
            int idx = tid + 256 * i;       // 0..511
            int row = idx >> 2;            // 0..127
            int c8  = (idx & 3) * 8;       // halves
            cp_async16(sa + (unsigned)(row * SASTH + c8) * 2u,
                       &A[(size_t)(bm + row) * GK + k0 + c8]);
            cp_async16(sb + (unsigned)(row * SASTH + c8) * 2u,
                       &B[(size_t)(bn + row) * GK + k0 + c8]);
        }
        cp_commit();
    };

    load_stage(0, 0);
    load_stage(1, 1);
    const int KT = GK / BKK;

    int st = 0;
    for (int kt = 0; kt < KT; kt++) {
        if (kt + 1 < KT) cp_wait1(); else cp_wait0();
        __syncthreads();
        if (kt + 2 < KT) {
            int s2 = st + 2; if (s2 >= 3) s2 -= 3;
            load_stage(s2, kt + 2);
        }

        unsigned sA = smem_base + (unsigned)(st * GSTGH) * 2u;
        unsigned sB = sA + (unsigned)GASZH * 2u;

#pragma unroll
        for (int ks = 0; ks < 2; ks++) {     // two k16 steps per BK=32
            int k0 = ks * 16;
            uint4 a[2], bp[4];
#pragma unroll
            for (int mi = 0; mi < 2; mi++)
                ldsm_x4(a[mi], sA + (unsigned)((a_row + mi*16) * SASTH
                                               + a_colh + k0) * 2u);
#pragma unroll
            for (int p = 0; p < 4; p++)
                ldsm_x4(bp[p], sB + (unsigned)((b_row + p*16) * SASTH
                                               + b_colh + k0) * 2u);
#pragma unroll
            for (int mi = 0; mi < 2; mi++)
#pragma unroll
                for (int p = 0; p < 4; p++) {
                    mma_f16(c[mi][2*p  ], a[mi], bp[p].x, bp[p].y);
                    mma_f16(c[mi][2*p+1], a[mi], bp[p].z, bp[p].w);
                }
        }
        if (++st == 3) st = 0;
    }

#pragma unroll
    for (int mi = 0; mi < 2; mi++) {
#pragma unroll
        for (int nj = 0; nj < 8; nj++) {
            int row0 = bm + wm + mi * 16 + g;
            int col  = bn + wn + nj * 8 + 2 * t;
            *(float2*)&C[(size_t)row0 * N + col] =
                make_float2(c[mi][nj][0], c[mi][nj][1]);
            *(float2*)&C[(size_t)(row0 + 8) * N + col] =
                make_float2(c[mi][nj][2], c[mi][nj][3]);
        }
    }
}

__global__ __launch_bounds__(256, 2) void qkv_gemm_kernel(
    const __half* __restrict__ A, const __half* __restrict__ B,
    float* __restrict__ C)
{
    gemm_f16(A, B, C, QKVW, blockIdx.y * 128, blockIdx.x * 128);
}

__global__ __launch_bounds__(256, 2) void oproj_gemm_kernel(
    const __half* __restrict__ A, const __half* __restrict__ B,
    float* __restrict__ C)
{
    gemm_f16(A, B, C, DIMD, blockIdx.y * 128, blockIdx.x * 128);
}

// ---------------------------------------------------------------------------
// Fused RoPE + fp16 convert: 24 virtual heads (16 Q rope+scale, 4 K rope,
// 4 V plain convert). Reads fp32 g_qkv, writes fp16 g_qkvh.
// ---------------------------------------------------------------------------
__global__ void rope_cvt_kernel(const float* __restrict__ qkv,
                                __half* __restrict__ qkvh,
                                const float* __restrict__ cs,
                                const float* __restrict__ sn, float qscale)
{
    int idx = blockIdx.x * blockDim.x + threadIdx.x;  // TT*24*64
    int i  = idx & 63;
    int hh = (idx >> 6) % 24;
    int t  = idx / (64 * 24);
    if (t >= TT) return;
    size_t base = (size_t)t * QKVW + hh * HD;
    const float* p = qkv + base;
    __half* o = qkvh + base;
    if (hh < 20) {   // Q or K: RoPE
        float c = cs[t * HD + i];
        float s = sn[t * HD + i];
        float scale = hh < NH ? qscale : 1.0f;
        float u1 = p[i], u2 = p[i + 64];
        o[i]      = __float2half_rn((u1 * c - u2 * s) * scale);
        o[i + 64] = __float2half_rn((u2 * c + u1 * s) * scale);
    } else {         // V: plain convert
        o[i]      = __float2half_rn(p[i]);
        o[i + 64] = __float2half_rn(p[i + 64]);
    }
}

// ---------------------------------------------------------------------------
// fp16 flash attention. BQ=128, BKV=64, 256 threads (8 warps, 16 q-rows each).
// S C-frag packs directly into PV A-frag (no shuffles); V via ldmatrix.trans.
// Persistent work-steal over all SMs.
// ---------------------------------------------------------------------------
#define FAQ 128
#define FA_ST 136                   // row stride (halves) for Q/K/V tiles
#define FA_QSZH (FAQ*FA_ST)         // 17408 halves
#define FA_KSZH (64*FA_ST)          // 8704
#define FA_KVSZH (2*FA_KSZH)        // K + V per stage
#define FA_SMEM ((FA_QSZH + 2*FA_KVSZH)*2)   // 104448 bytes
#define FA_ITEMS (NH * (TT/FAQ))    // 256

__global__ __launch_bounds__(256, 1) void fa_f16_kernel(__half* __restrict__ att)
{
    extern __shared__ float smf[];
    __half* smh = (__half*)smf;
    __shared__ unsigned s_item;
    int tid = threadIdx.x;
    int lane = tid & 31, wid = tid >> 5;
    int g = lane >> 2, t = lane & 3;
    int w16 = wid * 16;

    int lrow = lane & 7;
    int am   = lane >> 3;
    int qa_row  = w16 + ((am & 1) << 3) + lrow;  // Q A-frag
    int qa_colh = (am >> 1) << 3;
    int kb_row  = ((am >> 1) << 3) + lrow;       // K B-frag
    int kb_colh = (am & 1) << 3;
    int vb_row  = ((am & 1) << 3) + lrow;        // V B-frag (trans)
    int vb_colh = (am >> 1) << 3;

    unsigned smem_base = (unsigned)__cvta_generic_to_shared(smh);

    while (true) {
        if (tid == 0) s_item = atomicAdd(&g_ctr, 1u);
        __syncthreads();
        unsigned r = s_item;
        if (r >= FA_ITEMS) break;
        int qb = (TT/FAQ) - 1 - (int)(r >> 4);
        int h  = (int)(r & 15u);
        int g0 = h / REP;

        // Load Q tile (fp16): 128 rows x 16 segs of 8 halves
#pragma unroll
        for (int i = 0; i < 8; i++) {
            int idx = tid + 256 * i;       // 0..2047
            int rr = idx >> 4;
            int c8 = (idx & 15) * 8;
            *(uint4*)&smh[rr*FA_ST + c8] =
                *(const uint4*)&g_qkvh[(size_t)(qb*FAQ + rr) * QKVW + h*HD + c8];
        }

        auto load_kv = [&](int kb, int s) {
            const __half* Kg = &g_qkvh[(size_t)(kb*64) * QKVW + NQ + g0*HD];
            const __half* Vg = Kg + NKV;
            unsigned kbase = smem_base + (unsigned)(FA_QSZH + s*FA_KVSZH) * 2u;
            unsigned vbase = kbase + (unsigned)FA_KSZH * 2u;
#pragma unroll
            for (int i = 0; i < 4; i++) {
                int idx = tid + 256 * i;   // 0..1023
                int rr = idx >> 4;         // 0..63
                int c8 = (idx & 15) * 8;
                cp_async16(kbase + (unsigned)(rr*FA_ST + c8) * 2u,
                           Kg + (size_t)rr*QKVW + c8);
                cp_async16(vbase + (unsigned)(rr*FA_ST + c8) * 2u,
                           Vg + (size_t)rr*QKVW + c8);
            }
            cp_commit();
        };

        float o[16][4];
#pragma unroll
        for (int nj = 0; nj < 16; nj++)
#pragma unroll
            for (int rr = 0; rr < 4; rr++) o[nj][rr] = 0.f;
        float m0 = -1e30f, m1 = -1e30f, l0 = 0.f, l1 = 0.f;

        const int kb_max = 2*qb + 1;
        load_kv(0, 0);

        for (int kb = 0; kb <= kb_max; kb++) {
            if (kb < kb_max) { load_kv(kb + 1, (kb + 1) & 1); cp_wait1(); }
            else             { cp_wait0(); }
            __syncthreads();

            unsigned sK = smem_base + (unsigned)(FA_QSZH + (kb & 1)*FA_KVSZH) * 2u;
            unsigned sV = sK + (unsigned)FA_KSZH * 2u;

            float s[8][4];
#pragma unroll
            for (int nj = 0; nj < 8; nj++)
#pragma unroll
                for (int rr = 0; rr < 4; rr++) s[nj][rr] = 0.f;

            // ---- S = Q K^T : 8 k16 steps ----
#pragma unroll
            for (int ks = 0; ks < 8; ks++) {
                int k0 = ks * 16;
                uint4 a, bp[4];
                ldsm_x4(a, smem_base + (unsigned)(qa_row*FA_ST
                                                  + qa_colh + k0)*2u);
#pragma unroll
                for (int p = 0; p < 4; p++)
                    ldsm_x4(bp[p], sK + (unsigned)((kb_row + p*16)*FA_ST
                                                   + kb_colh + k0)*2u);
#pragma unroll
                for (int p = 0; p < 4; p++) {
                    mma_f16(s[2*p  ], a, bp[p].x, bp[p].y);
                    mma_f16(s[2*p+1], a, bp[p].z, bp[p].w);
                }
            }

            // ---- causal mask (near-diagonal blocks only) ----
            if (kb >= 2*qb) {
                int r0 = qb*FAQ + w16 + g, r1 = r0 + 8;
                int cb0 = kb*64 + 2*t;
#pragma unroll
                for (int nj = 0; nj < 8; nj++) {
                    int c0 = cb0 + nj*8, c1 = c0 + 1;
                    if (c0 > r0) s[nj][0] = -1e30f;
                    if (c1 > r0) s[nj][1] = -1e30f;
                    if (c0 > r1) s[nj][2] = -1e30f;
                    if (c1 > r1) s[nj][3] = -1e30f;
                }
            }

            // ---- online softmax ----
            float mx0 = -1e30f, mx1 = -1e30f;
#pragma unroll
            for (int nj = 0; nj < 8; nj++) {
                mx0 = fmaxf(mx0, fmaxf(s[nj][0], s[nj][1]));
                mx1 = fmaxf(mx1, fmaxf(s[nj][2], s[nj][3]));
            }
            mx0 = fmaxf(mx0, __shfl_xor_sync(0xffffffffu, mx0, 1));
            mx0 = fmaxf(mx0, __shfl_xor_sync(0xffffffffu, mx0, 2));
            mx1 = fmaxf(mx1, __shfl_xor_sync(0xffffffffu, mx1, 1));
            mx1 = fmaxf(mx1, __shfl_xor_sync(0xffffffffu, mx1, 2));
            float mn0 = fmaxf(m0, mx0), mn1 = fmaxf(m1, mx1);
            float al0 = __expf(m0 - mn0), al1 = __expf(m1 - mn1);
            m0 = mn0; m1 = mn1;

            float rs0 = 0.f, rs1 = 0.f;
#pragma unroll
            for (int nj = 0; nj < 8; nj++) {
                s[nj][0] = __expf(s[nj][0] - mn0);
                s[nj][1] = __expf(s[nj][1] - mn0);
                s[nj][2] = __expf(s[nj][2] - mn1);
                s[nj][3] = __expf(s[nj][3] - mn1);
                rs0 += s[nj][0] + s[nj][1];
                rs1 += s[nj][2] + s[nj][3];
            }
            rs0 += __shfl_xor_sync(0xffffffffu, rs0, 1);
            rs0 += __shfl_xor_sync(0xffffffffu, rs0, 2);
            rs1 += __shfl_xor_sync(0xffffffffu, rs1, 1);
            rs1 += __shfl_xor_sync(0xffffffffu, rs1, 2);
            l0 = l0 * al0 + rs0;
            l1 = l1 * al1 + rs1;

#pragma unroll
            for (int nj = 0; nj < 16; nj++) {
                o[nj][0] *= al0; o[nj][1] *= al0;
                o[nj][2] *= al1; o[nj][3] *= al1;
            }

            // ---- O += P @ V : C-frag of S packs directly into A-frag ----
#pragma unroll
            for (int kt = 0; kt < 4; kt++) {
                uint4 a;
                a.x = pack_h2(s[2*kt  ][0], s[2*kt  ][1]);
                a.y = pack_h2(s[2*kt  ][2], s[2*kt  ][3]);
                a.z = pack_h2(s[2*kt+1][0], s[2*kt+1][1]);
                a.w = pack_h2(s[2*kt+1][2], s[2*kt+1][3]);
#pragma unroll
                for (int q = 0; q < 8; q++) {
                    uint4 bp;
                    ldsm_x4_t(bp, sV + (unsigned)((16*kt + vb_row)*FA_ST
                                                  + q*16 + vb_colh)*2u);
                    mma_f16(o[2*q  ], a, bp.x, bp.y);
                    mma_f16(o[2*q+1], a, bp.z, bp.w);
                }
            }
            __syncthreads();
        }

        // ---- epilogue: normalize, write fp16 ----
        float il0 = 1.0f / l0, il1 = 1.0f / l1;
#pragma unroll
        for (int nj = 0; nj < 16; nj++) {
            int row0 = qb*FAQ + w16 + g;
            int col  = h*HD + nj*8 + 2*t;
            __half2 v0 = __floats2half2_rn(o[nj][0]*il0, o[nj][1]*il0);
            __half2 v1 = __floats2half2_rn(o[nj][2]*il1, o[nj][3]*il1);
            *(__half2*)&att[(size_t)row0 * NQ + col]       = v0;
            *(__half2*)&att[(size_t)(row0 + 8) * NQ + col] = v1;
        }
        __syncthreads();
    }
}

// ---------------------------------------------------------------------------
extern "C" void kernel_launch(void* const* d_in, const int* in_sizes, int n_in,
                              void* d_out, int out_size)
{
    const float* x  = (const float*)d_in[0];
    const float* wq = (const float*)d_in[1];
    const float* wk = (const float*)d_in[2];
    const float* wv = (const float*)d_in[3];
    const float* wo = (const float*)d_in[4];
    const float* cs = (const float*)d_in[5];
    const float* sn = (const float*)d_in[6];
    float* out = (float*)d_out;

    float *qkv; __half *qkvh, *atth, *xh, *wqkvh, *worh; void* ctr;
    cudaGetSymbolAddress((void**)&qkv,   g_qkv);
    cudaGetSymbolAddress((void**)&qkvh,  g_qkvh);
    cudaGetSymbolAddress((void**)&atth,  g_atth);
    cudaGetSymbolAddress((void**)&xh,    g_xh);
    cudaGetSymbolAddress((void**)&wqkvh, g_wqkvh);
    cudaGetSymbolAddress((void**)&worh,  g_worh);
    cudaGetSymbolAddress(&ctr,           g_ctr);

    static int nsm = 0;
    if (nsm == 0) {
        cudaDeviceGetAttribute(&nsm, cudaDevAttrMultiProcessorCount, 0);
        if (nsm <= 0) nsm = 148;
        cudaFuncSetAttribute(qkv_gemm_kernel,
            cudaFuncAttributeMaxDynamicSharedMemorySize, GEMM_SMEM);
        cudaFuncSetAttribute(oproj_gemm_kernel,
            cudaFuncAttributeMaxDynamicSharedMemorySize, GEMM_SMEM);
        cudaFuncSetAttribute(fa_f16_kernel,
            cudaFuncAttributeMaxDynamicSharedMemorySize, FA_SMEM);
    }

    // Round inputs once to fp16 (10-bit mantissa — same as tf32)
    round_all_kernel<<<(R_TOT + 255)/256, 256>>>(
        x, wq, wk, wv, wo, xh, wqkvh, worh);

    // Packed QKV projection (fp16 in, fp32 out)
    qkv_gemm_kernel<<<dim3(QKVW/128, TT/128), 256, GEMM_SMEM>>>(xh, wqkvh, qkv);

    // RoPE Q/K + single fp16 rounding of all FA operands
    const float scale = 0.08838834764831845f;  // 128^-0.5
    rope_cvt_kernel<<<(TT*24*64)/256, 256>>>(qkv, qkvh, cs, sn, scale);

    // fp16 flash attention, persistent work-steal
    cudaMemsetAsync(ctr, 0, sizeof(unsigned));
    fa_f16_kernel<<<dim3(nsm, 1), 256, FA_SMEM>>>(atth);

    // Output projection (fp16 in, fp32 out)
    oproj_gemm_kernel<<<dim3(DIMD/128, TT/128), 256, GEMM_SMEM>>>(atth, worh, out);
}

// round 11
// speedup vs baseline: 1.7426x; 1.0523x over previous
#include <cuda_runtime.h>
#include <cuda_fp16.h>
#include <math.h>
#include <stdint.h>

#define TT 2048
#define DIMD 2048
#define NH 16
#define NKVH 4
#define HD 128
#define NQ (NH*HD)     // 2048
#define NKV (NKVH*HD)  // 512
#define REP (NH/NKVH)  // 4
#define QKVW 3072

// Scratch (device globals; allocation in kernel_launch is forbidden)
__device__ float  g_qkv [TT*QKVW];    // fp32 QKV GEMM output
__device__ __half g_qkvh[TT*QKVW];    // fp16 Q(roped)|K(roped)|V
__device__ __half g_atth[TT*NQ];      // fp16 attention output
__device__ __half g_xh  [TT*DIMD];
__device__ __half g_wqkvh[QKVW*DIMD]; // rows: wq | wk | wv
__device__ __half g_worh[DIMD*NQ];
__device__ unsigned g_ctr;

// ---------------------------------------------------------------------------
// helpers
// ---------------------------------------------------------------------------
#define R_X   (TT*DIMD/4)
#define R_WQ  (NQ*DIMD/4)
#define R_WKV (NKV*DIMD/4)
#define R_TOT (R_X + R_WQ + 2*R_WKV + NQ*DIMD/4)

__global__ void round_all_kernel(const float* __restrict__ x,
                                 const float* __restrict__ wq,
                                 const float* __restrict__ wk,
                                 const float* __restrict__ wv,
                                 const float* __restrict__ wo,
                                 __half* __restrict__ xh,
                                 __half* __restrict__ wqkvh,
                                 __half* __restrict__ worh)
{
    int i = blockIdx.x * blockDim.x + threadIdx.x;
    if (i >= R_TOT) return;
    const float* in; __half* out; int j = i;
    if (j < R_X)                   { in = x;  out = xh; }
    else if ((j -= R_X)   < R_WQ)  { in = wq; out = wqkvh; }
    else if ((j -= R_WQ)  < R_WKV) { in = wk; out = wqkvh + (size_t)NQ*DIMD; }
    else if ((j -= R_WKV) < R_WKV) { in = wv; out = wqkvh + (size_t)(NQ+NKV)*DIMD; }
    else { j -= R_WKV;               in = wo; out = worh; }
    float4 v = ((const float4*)in)[j];
    __half2 h0 = __floats2half2_rn(v.x, v.y);
    __half2 h1 = __floats2half2_rn(v.z, v.w);
    ((__half2*)out)[2*j]   = h0;
    ((__half2*)out)[2*j+1] = h1;
}

__device__ __forceinline__ void cp_async16(unsigned saddr, const void* g) {
    asm volatile("cp.async.cg.shared.global [%0], [%1], 16;\n"
                 :: "r"(saddr), "l"(g));
}
__device__ __forceinline__ void cp_commit() {
    asm volatile("cp.async.commit_group;\n");
}
__device__ __forceinline__ void cp_wait0() {
    asm volatile("cp.async.wait_group 0;\n");
}
__device__ __forceinline__ void cp_wait1() {
    asm volatile("cp.async.wait_group 1;\n");
}

// fp16 mma m16n8k16, fp32 accum
__device__ __forceinline__ void mma_f16(float c[4], const uint4& a,
                                        unsigned b0, unsigned b1) {
    asm volatile(
        "mma.sync.aligned.m16n8k16.row.col.f32.f16.f16.f32 "
        "{%0,%1,%2,%3}, {%4,%5,%6,%7}, {%8,%9}, {%0,%1,%2,%3};\n"
        : "+f"(c[0]), "+f"(c[1]), "+f"(c[2]), "+f"(c[3])
        : "r"(a.x), "r"(a.y), "r"(a.z), "r"(a.w), "r"(b0), "r"(b1));
}

__device__ __forceinline__ void ldsm_x4(uint4& d, unsigned addr) {
    asm volatile(
        "ldmatrix.sync.aligned.m8n8.x4.shared.b16 {%0,%1,%2,%3}, [%4];\n"
        : "=r"(d.x), "=r"(d.y), "=r"(d.z), "=r"(d.w) : "r"(addr));
}
__device__ __forceinline__ void ldsm_x4_t(uint4& d, unsigned addr) {
    asm volatile(
        "ldmatrix.sync.aligned.m8n8.x4.trans.shared.b16 {%0,%1,%2,%3}, [%4];\n"
        : "=r"(d.x), "=r"(d.y), "=r"(d.z), "=r"(d.w) : "r"(addr));
}

__device__ __forceinline__ unsigned pack_h2(float lo, float hi) {
    __half2 h = __floats2half2_rn(lo, hi);
    return *reinterpret_cast<unsigned*>(&h);
}

// ---------------------------------------------------------------------------
// fp16 GEMM: C[2048,N](fp32) = A[2048,2048](fp16) * B[N,2048](fp16)^T.
// CTA 128x128, 256 threads (8 warps 4m x 2n), warp tile 32x64.
// BK=64 halves (4 k16 steps/iter, 32 barriers total), 3-stage ring, occ 2.
// ---------------------------------------------------------------------------
#define BKK 64
#define SASTH 72                 // smem row stride in halves (144 B)
#define GK 2048
#define GASZH (128*SASTH)        // 9216 halves per operand
#define GSTGH (2*GASZH)          // 18432 halves per stage
#define GEMM_SMEM (3*GSTGH*2)    // 110592 bytes

__device__ __forceinline__ void gemm_f16(
    const __half* __restrict__ A, const __half* __restrict__ B,
    float* __restrict__ C, int N, int bm, int bn)
{
    extern __shared__ float smf[];
    __half* smh = (__half*)smf;
    int tid = threadIdx.x;
    int lane = tid & 31, wid = tid >> 5;
    int wm = (wid & 3) * 32;
    int wn = (wid >> 2) * 64;
    int g = lane >> 2, t = lane & 3;

    int lrow = lane & 7;
    int am   = lane >> 3;
    int a_row  = wm + ((am & 1) << 3) + lrow;
    int a_colh = (am >> 1) << 3;
    int b_row  = wn + ((am >> 1) << 3) + lrow;
    int b_colh = (am & 1) << 3;

    unsigned smem_base = (unsigned)__cvta_generic_to_shared(smh);

    float c[2][8][4];
#pragma unroll
    for (int mi = 0; mi < 2; mi++)
#pragma unroll
        for (int nj = 0; nj < 8; nj++)
#pragma unroll
            for (int r = 0; r < 4; r++) c[mi][nj][r] = 0.f;

    auto load_stage = [&](int s, int kt) {
        int k0 = kt * BKK;
        unsigned sa = smem_base + (unsigned)(s * GSTGH) * 2u;
        unsigned sb = sa + (unsigned)GASZH * 2u;
#pragma unroll
        for (int i = 0; i < 4; i++) {
            int idx = tid + 256 * i;       // 0..1023
            int row = idx >> 3;            // 0..127
            int c8  = (idx & 7) * 8;       // halves 0..56
            cp_async16(sa + (unsigned)(row * SASTH + c8) * 2u,
                       &A[(size_t)(bm + row) * GK + k0 + c8]);
            cp_async16(sb + (unsigned)(row * SASTH + c8) * 2u,
                       &B[(size_t)(bn + row) * GK + k0 + c8]);
        }
        cp_commit();
    };

    load_stage(0, 0);
    load_stage(1, 1);
    const int KT = GK / BKK;   // 32

    int st = 0;
    for (int kt = 0; kt < KT; kt++) {
        if (kt + 1 < KT) cp_wait1(); else cp_wait0();
        __syncthreads();
        if (kt + 2 < KT) {
            int s2 = st + 2; if (s2 >= 3) s2 -= 3;
            load_stage(s2, kt + 2);
        }

        unsigned sA = smem_base + (unsigned)(st * GSTGH) * 2u;
        unsigned sB = sA + (unsigned)GASZH * 2u;

#pragma unroll
        for (int ks = 0; ks < 4; ks++) {     // four k16 steps per BK=64
            int k0 = ks * 16;
            uint4 a[2], bp[4];
#pragma unroll
            for (int mi = 0; mi < 2; mi++)
                ldsm_x4(a[mi], sA + (unsigned)((a_row + mi*16) * SASTH
                                               + a_colh + k0) * 2u);
#pragma unroll
            for (int p = 0; p < 4; p++)
                ldsm_x4(bp[p], sB + (unsigned)((b_row + p*16) * SASTH
                                               + b_colh + k0) * 2u);
#pragma unroll
            for (int mi = 0; mi < 2; mi++)
#pragma unroll
                for (int p = 0; p < 4; p++) {
                    mma_f16(c[mi][2*p  ], a[mi], bp[p].x, bp[p].y);
                    mma_f16(c[mi][2*p+1], a[mi], bp[p].z, bp[p].w);
                }
        }
        if (++st == 3) st = 0;
    }

#pragma unroll
    for (int mi = 0; mi < 2; mi++) {
#pragma unroll
        for (int nj = 0; nj < 8; nj++) {
            int row0 = bm + wm + mi * 16 + g;
            int col  = bn + wn + nj * 8 + 2 * t;
            *(float2*)&C[(size_t)row0 * N + col] =
                make_float2(c[mi][nj][0], c[mi][nj][1]);
            *(float2*)&C[(size_t)(row0 + 8) * N + col] =
                make_float2(c[mi][nj][2], c[mi][nj][3]);
        }
    }
}

__global__ __launch_bounds__(256, 2) void qkv_gemm_kernel(
    const __half* __restrict__ A, const __half* __restrict__ B,
    float* __restrict__ C)
{
    gemm_f16(A, B, C, QKVW, blockIdx.y * 128, blockIdx.x * 128);
}

__global__ __launch_bounds__(256, 2) void oproj_gemm_kernel(
    const __half* __restrict__ A, const __half* __restrict__ B,
    float* __restrict__ C)
{
    gemm_f16(A, B, C, DIMD, blockIdx.y * 128, blockIdx.x * 128);
}

// ---------------------------------------------------------------------------
// Fused RoPE + fp16 convert (24 virtual heads: 16 Q rope+scale, 4 K rope,
// 4 V plain convert). fp32 g_qkv -> fp16 g_qkvh.
// ---------------------------------------------------------------------------
__global__ void rope_cvt_kernel(const float* __restrict__ qkv,
                                __half* __restrict__ qkvh,
                                const float* __restrict__ cs,
                                const float* __restrict__ sn, float qscale)
{
    int idx = blockIdx.x * blockDim.x + threadIdx.x;  // TT*24*64
    int i  = idx & 63;
    int hh = (idx >> 6) % 24;
    int t  = idx / (64 * 24);
    if (t >= TT) return;
    size_t base = (size_t)t * QKVW + hh * HD;
    const float* p = qkv + base;
    __half* o = qkvh + base;
    if (hh < 20) {
        float c = cs[t * HD + i];
        float s = sn[t * HD + i];
        float scale = hh < NH ? qscale : 1.0f;
        float u1 = p[i], u2 = p[i + 64];
        o[i]      = __float2half_rn((u1 * c - u2 * s) * scale);
        o[i + 64] = __float2half_rn((u2 * c + u1 * s) * scale);
    } else {
        o[i]      = __float2half_rn(p[i]);
        o[i + 64] = __float2half_rn(p[i + 64]);
    }
}

// ---------------------------------------------------------------------------
// fp16 flash attention, SOFTWARE-PIPELINED PV: at iteration kb the warp
// issues QK(kb) and PV(kb-1) HMMAs back-to-back, THEN runs softmax(kb) —
// the serial softmax chain overlaps the PV tensor work. P(kb-1) is carried
// in 4 packed fp16 A-frags (ph). 3-stage KV ring keeps V(kb-1) live.
// BQ=128, BKV=64, 256 threads; persistent work-steal over all SMs.
// ---------------------------------------------------------------------------
#define FAQ 128
#define FA_ST 136                     // row stride (halves)
#define FA_QSZH (FAQ*FA_ST)           // 17408 halves
#define FA_KSZH (64*FA_ST)            // 8704
#define FA_KVSZH (2*FA_KSZH)          // K + V per stage = 17408 halves
#define FA_SMEM ((FA_QSZH + 3*FA_KVSZH)*2)   // 139264 bytes
#define FA_ITEMS (NH * (TT/FAQ))      // 256

__global__ __launch_bounds__(256, 1) void fa_f16_kernel(__half* __restrict__ att)
{
    extern __shared__ float smf[];
    __half* smh = (__half*)smf;
    __shared__ unsigned s_item;
    int tid = threadIdx.x;
    int lane = tid & 31, wid = tid >> 5;
    int g = lane >> 2, t = lane & 3;
    int w16 = wid * 16;

    int lrow = lane & 7;
    int am   = lane >> 3;
    int qa_row  = w16 + ((am & 1) << 3) + lrow;  // Q A-frag
    int qa_colh = (am >> 1) << 3;
    int kb_row  = ((am >> 1) << 3) + lrow;       // K B-frag
    int kb_colh = (am & 1) << 3;
    int vb_row  = ((am & 1) << 3) + lrow;        // V B-frag (trans)
    int vb_colh = (am >> 1) << 3;

    unsigned smem_base = (unsigned)__cvta_generic_to_shared(smh);

    while (true) {
        if (tid == 0) s_item = atomicAdd(&g_ctr, 1u);
        __syncthreads();
        unsigned r = s_item;
        if (r >= FA_ITEMS) break;
        int qb = (TT/FAQ) - 1 - (int)(r >> 4);
        int h  = (int)(r & 15u);
        int g0 = h / REP;
        const int kb_max = 2*qb + 1;

        auto load_kv = [&](int kb, int s) {
            const __half* Kg = &g_qkvh[(size_t)(kb*64) * QKVW + NQ + g0*HD];
            const __half* Vg = Kg + NKV;
            unsigned kbase = smem_base + (unsigned)(FA_QSZH + s*FA_KVSZH) * 2u;
            unsigned vbase = kbase + (unsigned)FA_KSZH * 2u;
#pragma unroll
            for (int i = 0; i < 4; i++) {
                int idx = tid + 256 * i;
                int rr = idx >> 4;
                int c8 = (idx & 15) * 8;
                cp_async16(kbase + (unsigned)(rr*FA_ST + c8) * 2u,
                           Kg + (size_t)rr*QKVW + c8);
                cp_async16(vbase + (unsigned)(rr*FA_ST + c8) * 2u,
                           Vg + (size_t)rr*QKVW + c8);
            }
            cp_commit();
        };

        load_kv(0, 0);   // KV(0) in flight while Q tile loads below

        // Load Q tile (fp16)
#pragma unroll
        for (int i = 0; i < 8; i++) {
            int idx = tid + 256 * i;
            int rr = idx >> 4;
            int c8 = (idx & 15) * 8;
            *(uint4*)&smh[rr*FA_ST + c8] =
                *(const uint4*)&g_qkvh[(size_t)(qb*FAQ + rr) * QKVW + h*HD + c8];
        }

        float o[16][4];
#pragma unroll
        for (int nj = 0; nj < 16; nj++)
#pragma unroll
            for (int rr = 0; rr < 4; rr++) o[nj][rr] = 0.f;
        float m0 = -1e30f, m1 = -1e30f, l0 = 0.f, l1 = 0.f;
        uint4 ph[4];     // packed P of previous block

        int stc = 0;     // kb % 3
        for (int kb = 0; kb <= kb_max; kb++) {
            cp_wait0();              // KV(kb) arrived
            __syncthreads();         // everyone done reading the ring slot
            if (kb < kb_max) {
                int sn_ = stc + 1; if (sn_ >= 3) sn_ -= 3;
                load_kv(kb + 1, sn_);
            }

            unsigned sK = smem_base + (unsigned)(FA_QSZH + stc*FA_KVSZH) * 2u;
            int stp = stc - 1; if (stp < 0) stp += 3;
            unsigned sVp = smem_base
                         + (unsigned)(FA_QSZH + stp*FA_KVSZH + FA_KSZH) * 2u;

            // ---- QK(kb) -> s : 8 k16 steps (tensor) ----
            float s[8][4];
#pragma unroll
            for (int nj = 0; nj < 8; nj++)
#pragma unroll
                for (int rr = 0; rr < 4; rr++) s[nj][rr] = 0.f;
#pragma unroll
            for (int ks = 0; ks < 8; ks++) {
                int k0 = ks * 16;
                uint4 a, bp[4];
                ldsm_x4(a, smem_base + (unsigned)(qa_row*FA_ST
                                                  + qa_colh + k0)*2u);
#pragma unroll
                for (int p = 0; p < 4; p++)
                    ldsm_x4(bp[p], sK + (unsigned)((kb_row + p*16)*FA_ST
                                                   + kb_colh + k0)*2u);
#pragma unroll
                for (int p = 0; p < 4; p++) {
                    mma_f16(s[2*p  ], a, bp[p].x, bp[p].y);
                    mma_f16(s[2*p+1], a, bp[p].z, bp[p].w);
                }
            }

            // ---- PV(kb-1): issued before softmax; overlaps it ----
            if (kb > 0) {
#pragma unroll
                for (int kt = 0; kt < 4; kt++) {
#pragma unroll
                    for (int q = 0; q < 8; q++) {
                        uint4 bp;
                        ldsm_x4_t(bp, sVp + (unsigned)((16*kt + vb_row)*FA_ST
                                                       + q*16 + vb_colh)*2u);
                        mma_f16(o[2*q  ], ph[kt], bp.x, bp.y);
                        mma_f16(o[2*q+1], ph[kt], bp.z, bp.w);
                    }
                }
            }

            // ---- causal mask (near-diagonal blocks only) ----
            if (kb >= 2*qb) {
                int r0 = qb*FAQ + w16 + g, r1 = r0 + 8;
                int cb0 = kb*64 + 2*t;
#pragma unroll
                for (int nj = 0; nj < 8; nj++) {
                    int c0 = cb0 + nj*8, c1 = c0 + 1;
                    if (c0 > r0) s[nj][0] = -1e30f;
                    if (c1 > r0) s[nj][1] = -1e30f;
                    if (c0 > r1) s[nj][2] = -1e30f;
                    if (c1 > r1) s[nj][3] = -1e30f;
                }
            }

            // ---- online softmax (FMA/MUFU — overlaps PV drain) ----
            float mx0 = -1e30f, mx1 = -1e30f;
#pragma unroll
            for (int nj = 0; nj < 8; nj++) {
                mx0 = fmaxf(mx0, fmaxf(s[nj][0], s[nj][1]));
                mx1 = fmaxf(mx1, fmaxf(s[nj][2], s[nj][3]));
            }
            mx0 = fmaxf(mx0, __shfl_xor_sync(0xffffffffu, mx0, 1));
            mx0 = fmaxf(mx0, __shfl_xor_sync(0xffffffffu, mx0, 2));
            mx1 = fmaxf(mx1, __shfl_xor_sync(0xffffffffu, mx1, 1));
            mx1 = fmaxf(mx1, __shfl_xor_sync(0xffffffffu, mx1, 2));
            float mn0 = fmaxf(m0, mx0), mn1 = fmaxf(m1, mx1);
            float al0 = __expf(m0 - mn0), al1 = __expf(m1 - mn1);
            m0 = mn0; m1 = mn1;

            float rs0 = 0.f, rs1 = 0.f;
#pragma unroll
            for (int nj = 0; nj < 8; nj++) {
                s[nj][0] = __expf(s[nj][0] - mn0);
                s[nj][1] = __expf(s[nj][1] - mn0);
                s[nj][2] = __expf(s[nj][2] - mn1);
                s[nj][3] = __expf(s[nj][3] - mn1);
                rs0 += s[nj][0] + s[nj][1];
                rs1 += s[nj][2] + s[nj][3];
            }
            rs0 += __shfl_xor_sync(0xffffffffu, rs0, 1);
            rs0 += __shfl_xor_sync(0xffffffffu, rs0, 2);
            rs1 += __shfl_xor_sync(0xffffffffu, rs1, 1);
            rs1 += __shfl_xor_sync(0xffffffffu, rs1, 2);
            l0 = l0 * al0 + rs0;
            l1 = l1 * al1 + rs1;

            // o rescale (waits on PV(kb-1) via scoreboard)
#pragma unroll
            for (int nj = 0; nj < 16; nj++) {
                o[nj][0] *= al0; o[nj][1] *= al0;
                o[nj][2] *= al1; o[nj][3] *= al1;
            }

            // pack P(kb) for next iteration's PV
#pragma unroll
            for (int kt = 0; kt < 4; kt++) {
                ph[kt].x = pack_h2(s[2*kt  ][0], s[2*kt  ][1]);
                ph[kt].y = pack_h2(s[2*kt  ][2], s[2*kt  ][3]);
                ph[kt].z = pack_h2(s[2*kt+1][0], s[2*kt+1][1]);
                ph[kt].w = pack_h2(s[2*kt+1][2], s[2*kt+1][3]);
            }

            if (++stc == 3) stc = 0;
        }

        // ---- final PV(kb_max) ----
        {
            int stl = kb_max % 3;
            unsigned sVl = smem_base
                         + (unsigned)(FA_QSZH + stl*FA_KVSZH + FA_KSZH) * 2u;
#pragma unroll
            for (int kt = 0; kt < 4; kt++) {
#pragma unroll
                for (int q = 0; q < 8; q++) {
                    uint4 bp;
                    ldsm_x4_t(bp, sVl + (unsigned)((16*kt + vb_row)*FA_ST
                                                   + q*16 + vb_colh)*2u);
                    mma_f16(o[2*q  ], ph[kt], bp.x, bp.y);
                    mma_f16(o[2*q+1], ph[kt], bp.z, bp.w);
                }
            }
        }

        // ---- epilogue: normalize, write fp16 ----
        float il0 = 1.0f / l0, il1 = 1.0f / l1;
#pragma unroll
        for (int nj = 0; nj < 16; nj++) {
            int row0 = qb*FAQ + w16 + g;
            int col  = h*HD + nj*8 + 2*t;
            __half2 v0 = __floats2half2_rn(o[nj][0]*il0, o[nj][1]*il0);
            __half2 v1 = __floats2half2_rn(o[nj][2]*il1, o[nj][3]*il1);
            *(__half2*)&att[(size_t)row0 * NQ + col]       = v0;
            *(__half2*)&att[(size_t)(row0 + 8) * NQ + col] = v1;
        }
        __syncthreads();
    }
}

// ---------------------------------------------------------------------------
extern "C" void kernel_launch(void* const* d_in, const int* in_sizes, int n_in,
                              void* d_out, int out_size)
{
    const float* x  = (const float*)d_in[0];
    const float* wq = (const float*)d_in[1];
    const float* wk = (const float*)d_in[2];
    const float* wv = (const float*)d_in[3];
    const float* wo = (const float*)d_in[4];
    const float* cs = (const float*)d_in[5];
    const float* sn = (const float*)d_in[6];
    float* out = (float*)d_out;

    float *qkv; __half *qkvh, *atth, *xh, *wqkvh, *worh; void* ctr;
    cudaGetSymbolAddress((void**)&qkv,   g_qkv);
    cudaGetSymbolAddress((void**)&qkvh,  g_qkvh);
    cudaGetSymbolAddress((void**)&atth,  g_atth);
    cudaGetSymbolAddress((void**)&xh,    g_xh);
    cudaGetSymbolAddress((void**)&wqkvh, g_wqkvh);
    cudaGetSymbolAddress((void**)&worh,  g_worh);
    cudaGetSymbolAddress(&ctr,           g_ctr);

    static int nsm = 0;
    if (nsm == 0) {
        cudaDeviceGetAttribute(&nsm, cudaDevAttrMultiProcessorCount, 0);
        if (nsm <= 0) nsm = 148;
        cudaFuncSetAttribute(qkv_gemm_kernel,
            cudaFuncAttributeMaxDynamicSharedMemorySize, GEMM_SMEM);
        cudaFuncSetAttribute(oproj_gemm_kernel,
            cudaFuncAttributeMaxDynamicSharedMemorySize, GEMM_SMEM);
        cudaFuncSetAttribute(fa_f16_kernel,
            cudaFuncAttributeMaxDynamicSharedMemorySize, FA_SMEM);
    }

    // Round inputs once to fp16 (10-bit mantissa — same as tf32)
    round_all_kernel<<<(R_TOT + 255)/256, 256>>>(
        x, wq, wk, wv, wo, xh, wqkvh, worh);

    // Packed QKV projection (fp16 in, fp32 out)
    qkv_gemm_kernel<<<dim3(QKVW/128, TT/128), 256, GEMM_SMEM>>>(xh, wqkvh, qkv);

    // RoPE Q/K + single fp16 rounding of all FA operands
    const float scale = 0.08838834764831845f;  // 128^-0.5
    rope_cvt_kernel<<<(TT*24*64)/256, 256>>>(qkv, qkvh, cs, sn, scale);

    // fp16 flash attention, persistent work-steal, pipelined PV
    cudaMemsetAsync(ctr, 0, sizeof(unsigned));
    fa_f16_kernel<<<dim3(nsm, 1), 256, FA_SMEM>>>(atth);

    // Output projection (fp16 in, fp32 out)
    oproj_gemm_kernel<<<dim3(DIMD/128, TT/128), 256, GEMM_SMEM>>>(atth, worh, out);
}